// round 10
// baseline (speedup 1.0000x reference)
#include <cuda_runtime.h>

#define NROWS 256
#define CHUNKS 49   // 12544 float4 per row / 256 threads per block

// Scratch (no cudaMalloc). __device__ globals zero-init at module load.
__device__ float d_rowsum[NROWS];
__device__ unsigned int d_done[NROWS];

// Kernel 1: reduce with the PROVEN 6.7TB/s launch shape (grid 49x256, one
// float4 per thread) and a near-zero epilogue: warp shfl reduce + lane0
// fire-and-forget global atomicAdd (REDG). No __syncthreads, no smem, no
// block tree, no finalize pass.
__global__ __launch_bounds__(256) void row_sum_kernel(const float* __restrict__ c1,
                                                      int row_elems) {
    const int row = blockIdx.y;
    const float4* p = reinterpret_cast<const float4*>(c1 + (size_t)row * row_elems);

    float4 v = p[blockIdx.x * 256 + threadIdx.x];
    float s = (v.x + v.y) + (v.z + v.w);

    #pragma unroll
    for (int o = 16; o > 0; o >>= 1)
        s += __shfl_xor_sync(0xffffffffu, s, o);

    if ((threadIdx.x & 31) == 0)
        atomicAdd(&d_rowsum[row], s);   // no return use -> REDG, fire & forget
}

// Kernel 2: proven R1 scale body (6.7 TB/s). Single broadcast sum load scaled
// by invJ. Last-finished block per row resets the accumulators for the next
// graph replay (counter bumped only AFTER m is read -> race-free reset).
__global__ __launch_bounds__(256) void scale_kernel(const float* __restrict__ c2,
                                                    float* __restrict__ out,
                                                    int row_elems, float invJ) {
    const int row = blockIdx.y;
    const float m = d_rowsum[row] * invJ;
    const size_t base = (size_t)row * row_elems;
    const float4* src = reinterpret_cast<const float4*>(c2 + base);
    float4* dst = reinterpret_cast<float4*>(out + base);
    const int i = blockIdx.x * blockDim.x + threadIdx.x;
    float4 v = src[i];
    v.x *= m; v.y *= m; v.z *= m; v.w *= m;
    dst[i] = v;

    __syncthreads();  // all threads have read m (compiled: m read at entry)
    if (threadIdx.x == 0) {
        unsigned int o = atomicAdd(&d_done[row], 1u);
        if (o == CHUNKS - 1) {        // last block of this row
            d_rowsum[row] = 0.f;      // safe: all 49 blocks already read m
            d_done[row] = 0;          // self-reset for next replay
        }
    }
}

extern "C" void kernel_launch(void* const* d_in, const int* in_sizes, int n_in,
                              void* d_out, int out_size) {
    const float* c1 = (const float*)d_in[0];
    const float* c2 = (const float*)d_in[1];
    float* out = (float*)d_out;

    const int row_elems = in_sizes[0] / NROWS;  // 50176
    const float invJ = 1.0f / (float)row_elems;

    dim3 grid(CHUNKS, NROWS);                   // 49 x 256 = 12544 blocks
    row_sum_kernel<<<grid, 256>>>(c1, row_elems);
    scale_kernel<<<grid, 256>>>(c2, out, row_elems, invJ);
}

// round 11
// speedup vs baseline: 2.9961x; 2.9961x over previous
#include <cuda_runtime.h>

#define NROWS 256
#define TPB   512

// One block per row: reduce row of conv1 -> mean -> scale row of conv2.
// No inter-block communication whatsoever. 256 blocks x 512 threads, 2 CTAs/SM
// -> entire grid resident in one wave on 148 SMs.
__global__ __launch_bounds__(TPB, 2) void fused_row_kernel(const float* __restrict__ c1,
                                                           const float* __restrict__ c2,
                                                           float* __restrict__ out,
                                                           int row_elems) {
    const int row = blockIdx.x;
    const int tid = threadIdx.x;
    const size_t row_base = (size_t)row * row_elems;
    const int n4 = row_elems >> 2;             // 12544 = 24.5 * 512

    // ---------------- Phase A: reduce conv1[row] ----------------
    const float4* p = reinterpret_cast<const float4*>(c1 + row_base);
    float s0 = 0.f, s1 = 0.f, s2 = 0.f, s3 = 0.f;

    if (n4 == 12544) {
        // 24 full strides of 512 = 6 iterations of 4 front-batched loads,
        // + half-stride tail (first 256 threads).
        #pragma unroll
        for (int k = 0; k < 6; k++) {
            const int b = k * 2048 + tid;
            float4 a0 = __ldcs(&p[b]);
            float4 a1 = __ldcs(&p[b + 512]);
            float4 a2 = __ldcs(&p[b + 1024]);
            float4 a3 = __ldcs(&p[b + 1536]);
            s0 += (a0.x + a0.y) + (a0.z + a0.w);
            s1 += (a1.x + a1.y) + (a1.z + a1.w);
            s2 += (a2.x + a2.y) + (a2.z + a2.w);
            s3 += (a3.x + a3.y) + (a3.z + a3.w);
        }
        if (tid < 256) {
            float4 a = __ldcs(&p[12288 + tid]);
            s0 += (a.x + a.y) + (a.z + a.w);
        }
    } else {
        for (int i = tid; i < n4; i += TPB) {
            float4 a = __ldcs(&p[i]);
            s0 += (a.x + a.y) + (a.z + a.w);
        }
    }
    float s = (s0 + s1) + (s2 + s3);

    #pragma unroll
    for (int o = 16; o > 0; o >>= 1)
        s += __shfl_xor_sync(0xffffffffu, s, o);

    __shared__ float warp_sums[16];
    __shared__ float s_mean;
    const int lane = tid & 31;
    const int wid  = tid >> 5;
    if (lane == 0) warp_sums[wid] = s;
    __syncthreads();
    if (tid == 0) {
        float t = 0.f;
        #pragma unroll
        for (int w = 0; w < 16; w++) t += warp_sums[w];  // fixed order: deterministic
        s_mean = t / (float)row_elems;
    }
    __syncthreads();
    const float m = s_mean;

    // ---------------- Phase B: out[row] = m * conv2[row] ----------------
    const float4* src = reinterpret_cast<const float4*>(c2 + row_base);
    float4* dst       = reinterpret_cast<float4*>(out + row_base);

    if (n4 == 12544) {
        #pragma unroll
        for (int k = 0; k < 6; k++) {
            const int b = k * 2048 + tid;
            float4 a0 = __ldcs(&src[b]);
            float4 a1 = __ldcs(&src[b + 512]);
            float4 a2 = __ldcs(&src[b + 1024]);
            float4 a3 = __ldcs(&src[b + 1536]);
            a0.x *= m; a0.y *= m; a0.z *= m; a0.w *= m;
            a1.x *= m; a1.y *= m; a1.z *= m; a1.w *= m;
            a2.x *= m; a2.y *= m; a2.z *= m; a2.w *= m;
            a3.x *= m; a3.y *= m; a3.z *= m; a3.w *= m;
            __stcs(&dst[b],        a0);
            __stcs(&dst[b + 512],  a1);
            __stcs(&dst[b + 1024], a2);
            __stcs(&dst[b + 1536], a3);
        }
        if (tid < 256) {
            float4 a = __ldcs(&src[12288 + tid]);
            a.x *= m; a.y *= m; a.z *= m; a.w *= m;
            __stcs(&dst[12288 + tid], a);
        }
    } else {
        for (int i = tid; i < n4; i += TPB) {
            float4 a = __ldcs(&src[i]);
            a.x *= m; a.y *= m; a.z *= m; a.w *= m;
            __stcs(&dst[i], a);
        }
    }
}

extern "C" void kernel_launch(void* const* d_in, const int* in_sizes, int n_in,
                              void* d_out, int out_size) {
    const float* c1 = (const float*)d_in[0];
    const float* c2 = (const float*)d_in[1];
    float* out = (float*)d_out;

    const int row_elems = in_sizes[0] / NROWS;  // 50176

    fused_row_kernel<<<NROWS, TPB>>>(c1, c2, out, row_elems);
}